// round 4
// baseline (speedup 1.0000x reference)
#include <cuda_runtime.h>
#include <math.h>

// Shapes (fixed by the problem)
#define Bc   16
#define Hc   32
#define Dh   128
#define HALF 64
#define NTHREADS 256
#define NWARPS   8
#define UNROLL   4

// out[b, h*128 + d] = softmax(q_r . K / sqrt(D)) . V   over 4096 kv positions
__global__ __launch_bounds__(NTHREADS, 4)
void decode_attn_kernel(const float* __restrict__ q,
                        const float* __restrict__ k,
                        const float* __restrict__ v,
                        const float* __restrict__ cache_k,
                        const float* __restrict__ cache_v,
                        float* __restrict__ out,
                        int past)
{
    const int bh   = blockIdx.x;
    const int b    = bh / Hc;
    const int h    = bh % Hc;
    const int tid  = threadIdx.x;
    const int wid  = tid >> 5;
    const int lane = tid & 31;

    __shared__ float s_q[Dh];
    __shared__ float s_k[Dh];
    __shared__ float s_v[Dh];
    __shared__ float s_m[NWARPS];
    __shared__ float s_l[NWARPS];
    __shared__ float s_acc[NWARPS][Dh];

    // ---- Prologue: RoPE-rotate q and the new k token for this (b,h) ----
    const float* qp = q + (size_t)(b * Hc + h) * Dh;
    const float* kp = k + (size_t)(b * Hc + h) * Dh;
    const float* vp = v + (size_t)(b * Hc + h) * Dh;

    if (tid < Dh) {
        const int d = tid;
        const int i = (d < HALF) ? d : d - HALF;
        // inv_freq = theta^(-i/64); angle = pos * inv_freq  (pos = past_len)
        double inv = pow(10000.0, -(double)i / (double)HALF);
        double ang = (double)past * inv;
        double cd, sd;
        sincos(ang, &sd, &cd);
        const float c = (float)cd, s = (float)sd;
        if (d < HALF) {
            s_q[d] = qp[d] * c - qp[d + HALF] * s;
            s_k[d] = kp[d] * c - kp[d + HALF] * s;
        } else {
            s_q[d] = qp[d] * c + qp[d - HALF] * s;
            s_k[d] = kp[d] * c + kp[d - HALF] * s;
        }
        s_v[d] = vp[d];
    }
    __syncthreads();

    // Each lane owns 4 contiguous dims of the head
    const float4 q4 = *reinterpret_cast<const float4*>(&s_q[lane * 4]);
    const float4 k_new = *(reinterpret_cast<const float4*>(s_k) + lane);
    const float4 v_new = *(reinterpret_cast<const float4*>(s_v) + lane);
    const float scale = rsqrtf((float)Dh);

    // cache_k layout: [B, past, H, D]; row (b, j, h) = base + j*H*D
    const size_t rowstride = (size_t)Hc * Dh;
    const float* ck = cache_k + ((size_t)b * past * Hc + h) * Dh;
    const float* cv = cache_v + ((size_t)b * past * Hc + h) * Dh;

    const int total = past + 1;   // 4096: all positions valid (kv_pos <= pos)

    float m = -INFINITY;
    float l = 0.0f;
    float4 acc = make_float4(0.f, 0.f, 0.f, 0.f);

    // Warp w handles rows [w*U + it*32, ...): 4 rows per iteration, 8 loads in flight
    for (int base = wid * UNROLL; base < total; base += NWARPS * UNROLL) {
        float4 k4[UNROLL], v4[UNROLL];
        #pragma unroll
        for (int u = 0; u < UNROLL; u++) {
            const int j = base + u;
            if (j < past) {
                const size_t off = (size_t)j * rowstride;
                k4[u] = *(reinterpret_cast<const float4*>(ck + off) + lane);
                v4[u] = *(reinterpret_cast<const float4*>(cv + off) + lane);
            } else if (j == past) {
                k4[u] = k_new;
                v4[u] = v_new;
            } else {
                k4[u] = make_float4(0.f, 0.f, 0.f, 0.f);
                v4[u] = make_float4(0.f, 0.f, 0.f, 0.f);
            }
        }

        float sc[UNROLL];
        #pragma unroll
        for (int u = 0; u < UNROLL; u++) {
            float d = q4.x * k4[u].x + q4.y * k4[u].y
                    + q4.z * k4[u].z + q4.w * k4[u].w;
            #pragma unroll
            for (int o = 16; o > 0; o >>= 1)
                d += __shfl_xor_sync(0xffffffffu, d, o);
            sc[u] = (base + u <= past) ? d * scale : -INFINITY;
        }

        float mnew = m;
        #pragma unroll
        for (int u = 0; u < UNROLL; u++) mnew = fmaxf(mnew, sc[u]);

        const float corr = __expf(m - mnew);
        l *= corr;
        acc.x *= corr; acc.y *= corr; acc.z *= corr; acc.w *= corr;

        #pragma unroll
        for (int u = 0; u < UNROLL; u++) {
            const float p = __expf(sc[u] - mnew);
            l += p;
            acc.x += p * v4[u].x;
            acc.y += p * v4[u].y;
            acc.z += p * v4[u].z;
            acc.w += p * v4[u].w;
        }
        m = mnew;
    }

    // ---- Cross-warp flash combine ----
    if (lane == 0) { s_m[wid] = m; s_l[wid] = l; }
    *reinterpret_cast<float4*>(&s_acc[wid][lane * 4]) = acc;
    __syncthreads();

    if (tid < Dh) {
        float M = -INFINITY;
        #pragma unroll
        for (int w = 0; w < NWARPS; w++) M = fmaxf(M, s_m[w]);
        float L = 0.f, o = 0.f;
        #pragma unroll
        for (int w = 0; w < NWARPS; w++) {
            const float e = __expf(s_m[w] - M);
            L += s_l[w] * e;
            o += s_acc[w][tid] * e;
        }
        out[(size_t)b * (Hc * Dh) + h * Dh + tid] = o / L;
    }
}

extern "C" void kernel_launch(void* const* d_in, const int* in_sizes, int n_in,
                              void* d_out, int out_size)
{
    const float* q       = (const float*)d_in[0];
    const float* k       = (const float*)d_in[1];
    const float* v       = (const float*)d_in[2];
    const float* cache_k = (const float*)d_in[3];
    const float* cache_v = (const float*)d_in[4];
    (void)n_in; (void)out_size;

    // past = cache length, derived from cache_k element count [B, past, H, D]
    const int past = in_sizes[3] / (Bc * Hc * Dh);

    decode_attn_kernel<<<Bc * Hc, NTHREADS>>>(q, k, v, cache_k, cache_v,
                                              (float*)d_out, past);
}